// round 13
// baseline (speedup 1.0000x reference)
#include <cuda_runtime.h>
#include <cuda_bf16.h>

// Problem constants
#define B_  32
#define SQ  512
#define D_  768
#define H_  12
#define E_  64
#define M1  (B_*SQ)   // 16384

typedef unsigned long long u64;
typedef unsigned int u32;

// ---------------------------------------------------------------------------
// Scratch (device globals per harness rules — no allocations allowed)
// ---------------------------------------------------------------------------
__device__ __nv_bfloat16 g_x_hi [(size_t)M1 * D_];          // 25 MB
__device__ __nv_bfloat16 g_x_lo [(size_t)M1 * D_];          // 25 MB
__device__ __nv_bfloat16 g_qt_hi[(size_t)H_ * D_ * D_];     // 14 MB  (Q^T: [h][e][d])
__device__ __nv_bfloat16 g_qt_lo[(size_t)H_ * D_ * D_];     // 14 MB
__device__ __nv_bfloat16 g_vt_hi[(size_t)H_ * E_ * D_];     // 1.2 MB (V^T: [h][e][d])
__device__ __nv_bfloat16 g_vt_lo[(size_t)H_ * E_ * D_];
__device__ __nv_bfloat16 g_q_hi [(size_t)H_ * M1 * D_];     // 302 MB (q split, K-major for G2)
__device__ __nv_bfloat16 g_q_lo [(size_t)H_ * M1 * D_];     // 302 MB
__device__ float g_s [(size_t)B_ * H_ * SQ * SQ];           // 402 MB
__device__ __nv_bfloat16 g_xvt_hi[(size_t)B_ * H_ * E_ * SQ]; // 25 MB (xv^T: [z][e][m])
__device__ __nv_bfloat16 g_xvt_lo[(size_t)B_ * H_ * E_ * SQ];

// ---------------------------------------------------------------------------
// Portable (compute_103 baseline) tensor-core + async-copy helpers
// ---------------------------------------------------------------------------
__device__ __forceinline__ u32 smem_u32(const void* p) {
    u32 a;
    asm("{ .reg .u64 t; cvta.to.shared.u64 t, %1; cvt.u32.u64 %0, t; }" : "=r"(a) : "l"(p));
    return a;
}
__device__ __forceinline__ void cp16(u32 dst, const void* src) {
    asm volatile("cp.async.cg.shared.global [%0], [%1], 16;" :: "r"(dst), "l"(src) : "memory");
}
#define CP_COMMIT() asm volatile("cp.async.commit_group;" ::: "memory")
#define CP_WAIT(n)  asm volatile("cp.async.wait_group %0;" :: "n"(n) : "memory")

__device__ __forceinline__ void ldm4(u32* r, u32 addr) {
    asm volatile("ldmatrix.sync.aligned.m8n8.x4.shared.b16 {%0,%1,%2,%3}, [%4];"
        : "=r"(r[0]), "=r"(r[1]), "=r"(r[2]), "=r"(r[3]) : "r"(addr));
}
__device__ __forceinline__ void mma16816(float* c, const u32* a, u32 b0, u32 b1) {
    asm volatile(
        "mma.sync.aligned.m16n8k16.row.col.f32.bf16.bf16.f32 "
        "{%0,%1,%2,%3}, {%4,%5,%6,%7}, {%8,%9}, {%0,%1,%2,%3};"
        : "+f"(c[0]), "+f"(c[1]), "+f"(c[2]), "+f"(c[3])
        : "r"(a[0]), "r"(a[1]), "r"(a[2]), "r"(a[3]), "r"(b0), "r"(b1));
}
__device__ __forceinline__ void split2(float f0, float f1, u32& hp, u32& lp) {
    __nv_bfloat16 h0 = __float2bfloat16(f0);
    __nv_bfloat16 h1 = __float2bfloat16(f1);
    __nv_bfloat16 l0 = __float2bfloat16(f0 - __bfloat162float(h0));
    __nv_bfloat16 l1 = __float2bfloat16(f1 - __bfloat162float(h1));
    hp = (u32)__bfloat16_as_ushort(h0) | ((u32)__bfloat16_as_ushort(h1) << 16);
    lp = (u32)__bfloat16_as_ushort(l0) | ((u32)__bfloat16_as_ushort(l1) << 16);
}

// ---------------------------------------------------------------------------
// mma.sync GEMM:  C[128,128] = A[128,768] * B[128,768]^T  (split-bf16, 3 products)
// A, B K-major. 512 threads = 16 warps (4m x 4n), warp tile 32x32,
// 3-stage cp.async, product-major mma ordering for ILP.
// ---------------------------------------------------------------------------
#define KC     64
#define NCH    (D_/KC)               // 12
#define PITCH  72                    // halves per smem row (64 + 8 pad)
#define ARR    (128*PITCH)
#define BUFH   (4*ARR)               // halves per stage (Ahi,Alo,Bhi,Blo)
#define NSTG   3
#define SMEM_MMA (NSTG*BUFH*2)       // 221184 bytes
#define GTHREADS 512

template<int MODE>   // 0: split-bf16 output (G1) ; 1: fp32 output (G2)
__device__ __forceinline__ void mma_gemm_body(
    const __nv_bfloat16* __restrict__ Ahi, const __nv_bfloat16* __restrict__ Alo,
    const __nv_bfloat16* __restrict__ Bhi, const __nv_bfloat16* __restrict__ Blo,
    __nv_bfloat16* __restrict__ ohi, __nv_bfloat16* __restrict__ olo,
    float* __restrict__ of, int ldo)
{
    extern __shared__ __align__(16) char smem[];
    const u32 sb = smem_u32(smem);
    const int tid = threadIdx.x, lane = tid & 31, wid = tid >> 5;
    const int wm0 = (wid >> 2) * 32;       // 4 m-warps
    const int wn0 = (wid & 3) * 32;        // 4 n-warps

    float acc[2][4][4];
    #pragma unroll
    for (int f = 0; f < 2; f++)
        #pragma unroll
        for (int n = 0; n < 4; n++)
            #pragma unroll
            for (int j = 0; j < 4; j++) acc[f][n][j] = 0.f;

    const __nv_bfloat16* srcs[4] = { Ahi, Alo, Bhi, Blo };

    auto load_stage = [&](int buf, int c) {
        #pragma unroll
        for (int a4 = 0; a4 < 4; ++a4) {
            u32 dbase = sb + buf * (BUFH * 2) + a4 * (ARR * 2);
            const __nv_bfloat16* s = srcs[a4] + (size_t)c * KC;
            #pragma unroll
            for (int p = 0; p < 2; ++p) {
                int i = tid + p * GTHREADS;
                int r = i >> 3, q = i & 7;
                cp16(dbase + r * (PITCH * 2) + q * 16, s + (size_t)r * D_ + q * 8);
            }
        }
    };

    const u32 a_off = (u32)((wm0 + (lane & 15)) * PITCH + ((lane < 16) ? 0 : 8));
    const u32 b_off = (u32)(2 * ARR + (wn0 + (lane & 7) + ((lane >= 16) ? 8 : 0)) * PITCH
                            + ((lane & 8) ? 8 : 0));

    load_stage(0, 0); CP_COMMIT();
    load_stage(1, 1); CP_COMMIT();

    for (int c = 0; c < NCH; ++c) {
        if (c + 1 < NCH) { CP_WAIT(1); } else { CP_WAIT(0); }
        __syncthreads();
        if (c + 2 < NCH) { load_stage((c + 2) % NSTG, c + 2); CP_COMMIT(); }

        const u32 base = sb + (c % NSTG) * (BUFH * 2);
        #pragma unroll
        for (int t = 0; t < KC / 16; ++t) {
            u32 af[2][2][4];
            #pragma unroll
            for (int s = 0; s < 2; ++s)
                #pragma unroll
                for (int f = 0; f < 2; ++f)
                    ldm4(af[s][f], base + 2 * (s * ARR + a_off + f * (16 * PITCH) + t * 16));
            u32 bf_[2][2][4];
            #pragma unroll
            for (int s = 0; s < 2; ++s)
                #pragma unroll
                for (int p = 0; p < 2; ++p)
                    ldm4(bf_[s][p], base + 2 * (s * ARR + b_off + p * (16 * PITCH) + t * 16));

            // product-major: consecutive mmas hit different accumulators (ILP)
            #pragma unroll
            for (int f = 0; f < 2; ++f)
                #pragma unroll
                for (int n = 0; n < 4; ++n) {
                    const int p = n >> 1, hh = (n & 1) * 2;
                    mma16816(acc[f][n], af[0][f], bf_[0][p][hh], bf_[0][p][hh + 1]); // hi*hi
                }
            #pragma unroll
            for (int f = 0; f < 2; ++f)
                #pragma unroll
                for (int n = 0; n < 4; ++n) {
                    const int p = n >> 1, hh = (n & 1) * 2;
                    mma16816(acc[f][n], af[0][f], bf_[1][p][hh], bf_[1][p][hh + 1]); // hi*lo
                }
            #pragma unroll
            for (int f = 0; f < 2; ++f)
                #pragma unroll
                for (int n = 0; n < 4; ++n) {
                    const int p = n >> 1, hh = (n & 1) * 2;
                    mma16816(acc[f][n], af[1][f], bf_[0][p][hh], bf_[0][p][hh + 1]); // lo*hi
                }
        }
    }

    const int g = lane >> 2, cc = lane & 3;
    #pragma unroll
    for (int f = 0; f < 2; ++f)
        #pragma unroll
        for (int n = 0; n < 4; ++n) {
            const int r0 = wm0 + f * 16 + g;
            const int r1 = r0 + 8;
            const int col = wn0 + n * 8 + cc * 2;
            const float* c4 = acc[f][n];
            if (MODE == 0) {
                u32 hp, lp;
                split2(c4[0], c4[1], hp, lp);
                *(u32*)(ohi + (size_t)r0 * ldo + col) = hp;
                *(u32*)(olo + (size_t)r0 * ldo + col) = lp;
                split2(c4[2], c4[3], hp, lp);
                *(u32*)(ohi + (size_t)r1 * ldo + col) = hp;
                *(u32*)(olo + (size_t)r1 * ldo + col) = lp;
            } else {
                *(float2*)(of + (size_t)r0 * ldo + col) = make_float2(c4[0], c4[1]);
                *(float2*)(of + (size_t)r1 * ldo + col) = make_float2(c4[2], c4[3]);
            }
        }
}

// G1: q[h][m][n] = x[m][:] . qt[h][n][:]   grid(6, 128, 12)
__global__ __launch_bounds__(GTHREADS, 1) void k_mma_g1() {
    const int h = blockIdx.z;
    const size_t m0 = (size_t)blockIdx.y * 128;
    const size_t n0 = (size_t)blockIdx.x * 128;
    mma_gemm_body<0>(
        g_x_hi + m0 * D_, g_x_lo + m0 * D_,
        g_qt_hi + ((size_t)h * D_ + n0) * D_, g_qt_lo + ((size_t)h * D_ + n0) * D_,
        g_q_hi + (size_t)h * M1 * D_ + m0 * D_ + n0,
        g_q_lo + (size_t)h * M1 * D_ + m0 * D_ + n0,
        nullptr, D_);
}

// G2: S[b,h][n][m] = q[h][b*512+n][:] . x[b*512+m][:]   grid(4, 4, 384)
__global__ __launch_bounds__(GTHREADS, 1) void k_mma_g2() {
    const int z = blockIdx.z, b = z / H_, h = z % H_;
    const size_t m0 = (size_t)blockIdx.y * 128;
    const size_t n0 = (size_t)blockIdx.x * 128;
    const size_t arow = (size_t)h * M1 * D_ + ((size_t)b * SQ + m0) * D_;
    const size_t brow = ((size_t)b * SQ + n0) * D_;
    mma_gemm_body<1>(
        g_q_hi + arow, g_q_lo + arow,
        g_x_hi + brow, g_x_lo + brow,
        nullptr, nullptr,
        g_s + (size_t)z * SQ * SQ + m0 * SQ + n0, SQ);
}

// ---------------------------------------------------------------------------
// G3 (mma): xv^T[z][e][m] = (x_b[m][:] . vt[h][e][:])^T   tile 128m x 64e
// 8 warps (4m x 2n), warp tile 32x32, 2-stage cp.async. grid(4, 384)
// ---------------------------------------------------------------------------
#define S3AH (128*PITCH)             // halves per A split array
#define S3BH (64*PITCH)              // halves per B split array
#define S3H  (2*S3AH + 2*S3BH)       // stage halves = 27648
#define SMEM_G3 (2*S3H*2)            // 110592 bytes

__global__ __launch_bounds__(256, 1) void k_mma_g3() {
    extern __shared__ __align__(16) char smem[];
    const u32 sb = smem_u32(smem);
    const int z = blockIdx.y, b = z / H_, h = z % H_;
    const size_t m0 = (size_t)blockIdx.x * 128;
    const int tid = threadIdx.x, lane = tid & 31, wid = tid >> 5;
    const int wm0 = (wid >> 1) * 32;
    const int wn0 = (wid & 1) * 32;

    const __nv_bfloat16* Ahi = g_x_hi + ((size_t)b * SQ + m0) * D_;
    const __nv_bfloat16* Alo = g_x_lo + ((size_t)b * SQ + m0) * D_;
    const __nv_bfloat16* Bhi = g_vt_hi + (size_t)h * E_ * D_;
    const __nv_bfloat16* Blo = g_vt_lo + (size_t)h * E_ * D_;

    float acc[2][4][4];
    #pragma unroll
    for (int f = 0; f < 2; f++)
        #pragma unroll
        for (int n = 0; n < 4; n++)
            #pragma unroll
            for (int j = 0; j < 4; j++) acc[f][n][j] = 0.f;

    auto load_stage = [&](int buf, int c) {
        const u32 db = sb + buf * (S3H * 2);
        #pragma unroll
        for (int p = 0; p < 8; ++p) {        // A: 2 splits x 128 rows x 8 quads
            int i = tid + p * 256;
            int s = i >> 10, r = (i >> 3) & 127, q = i & 7;
            const __nv_bfloat16* src = (s ? Alo : Ahi) + (size_t)r * D_ + c * KC + q * 8;
            cp16(db + 2 * (s * S3AH + r * PITCH + q * 8), src);
        }
        #pragma unroll
        for (int p = 0; p < 4; ++p) {        // B: 2 splits x 64 rows x 8 quads
            int i = tid + p * 256;
            int s = i >> 9, r = (i >> 3) & 63, q = i & 7;
            const __nv_bfloat16* src = (s ? Blo : Bhi) + (size_t)r * D_ + c * KC + q * 8;
            cp16(db + 2 * (2 * S3AH + s * S3BH + r * PITCH + q * 8), src);
        }
    };

    const u32 a_off = (u32)((wm0 + (lane & 15)) * PITCH + ((lane < 16) ? 0 : 8));
    const u32 b_off = (u32)(2 * S3AH + (wn0 + (lane & 7) + ((lane >= 16) ? 8 : 0)) * PITCH
                            + ((lane & 8) ? 8 : 0));

    load_stage(0, 0); CP_COMMIT();
    for (int c = 0; c < NCH; ++c) {
        const int buf = c & 1;
        if (c + 1 < NCH) { load_stage(buf ^ 1, c + 1); CP_COMMIT(); CP_WAIT(1); }
        else             { CP_WAIT(0); }
        __syncthreads();
        const u32 base = sb + buf * (S3H * 2);
        #pragma unroll
        for (int t = 0; t < KC / 16; ++t) {
            u32 af[2][2][4];
            #pragma unroll
            for (int s = 0; s < 2; ++s)
                #pragma unroll
                for (int f = 0; f < 2; ++f)
                    ldm4(af[s][f], base + 2 * (s * S3AH + a_off + f * (16 * PITCH) + t * 16));
            u32 bf_[2][2][4];
            #pragma unroll
            for (int s = 0; s < 2; ++s)
                #pragma unroll
                for (int p = 0; p < 2; ++p)
                    ldm4(bf_[s][p], base + 2 * (s * S3BH + b_off + p * (16 * PITCH) + t * 16));
            #pragma unroll
            for (int f = 0; f < 2; ++f)
                #pragma unroll
                for (int n = 0; n < 4; ++n) {
                    const int p = n >> 1, hh = (n & 1) * 2;
                    mma16816(acc[f][n], af[0][f], bf_[0][p][hh], bf_[0][p][hh + 1]);
                }
            #pragma unroll
            for (int f = 0; f < 2; ++f)
                #pragma unroll
                for (int n = 0; n < 4; ++n) {
                    const int p = n >> 1, hh = (n & 1) * 2;
                    mma16816(acc[f][n], af[0][f], bf_[1][p][hh], bf_[1][p][hh + 1]);
                }
            #pragma unroll
            for (int f = 0; f < 2; ++f)
                #pragma unroll
                for (int n = 0; n < 4; ++n) {
                    const int p = n >> 1, hh = (n & 1) * 2;
                    mma16816(acc[f][n], af[1][f], bf_[0][p][hh], bf_[0][p][hh + 1]);
                }
        }
        __syncthreads();
    }

    // transposed split epilogue -> xvt[z][e][m]
    const int g = lane >> 2, cc = lane & 3;
    __nv_bfloat16* oh = g_xvt_hi + (size_t)z * E_ * SQ;
    __nv_bfloat16* ol = g_xvt_lo + (size_t)z * E_ * SQ;
    #pragma unroll
    for (int f = 0; f < 2; ++f)
        #pragma unroll
        for (int n = 0; n < 4; ++n) {
            const int r0 = wm0 + f * 16 + g;
            const int r1 = r0 + 8;
            const int col = wn0 + n * 8 + cc * 2;
            const float* c4 = acc[f][n];
            #pragma unroll
            for (int j = 0; j < 4; ++j) {
                const int r = (j < 2) ? r0 : r1;
                const int cl = col + (j & 1);
                float v = c4[j];
                __nv_bfloat16 hi = __float2bfloat16(v);
                oh[(size_t)cl * SQ + m0 + r] = hi;
                ol[(size_t)cl * SQ + m0 + r] = __float2bfloat16(v - __bfloat162float(hi));
            }
        }
}

// ---------------------------------------------------------------------------
// G4 fused: out_tile = softmax(S_tile_rows) @ xv   per (z, 128-query-block)
// 8 warps (4m x 2n), warp tile 32x32. B (xv^T) fully preloaded; A (p-tilde)
// converted chunk-by-chunk from S with deferred 1/l normalization. grid(4, 384)
// ---------------------------------------------------------------------------
#define G4_BH   (2*64*PITCH)                 // halves per B chunk (2 splits)
#define G4_BALL (8*G4_BH)                    // 73728 halves
#define G4_AH   (128*PITCH)                  // halves per A split
#define G4_LOFF ((G4_BALL + 2*G4_AH)*2)      // byte offset of linv[128]
#define SMEM_G4 (G4_LOFF + 128*4)            // 184832 bytes

__global__ __launch_bounds__(256, 1) void k_g4_fused(float* __restrict__ out) {
    extern __shared__ __align__(16) char smem[];
    const u32 sb = smem_u32(smem);
    u32* smw = (u32*)smem;
    float* sm_linv = (float*)(smem + G4_LOFF);

    const int z = blockIdx.y, b = z / H_, h = z % H_;
    const int n0 = blockIdx.x * 128;
    const int tid = threadIdx.x, lane = tid & 31, wid = tid >> 5;
    const int wm0 = (wid >> 1) * 32;
    const int wn0 = (wid & 1) * 32;

    // preload all of B = xvt[z] (64 x 512, 2 splits) via cp.async
    {
        const __nv_bfloat16* bh = g_xvt_hi + (size_t)z * E_ * SQ;
        const __nv_bfloat16* bl = g_xvt_lo + (size_t)z * E_ * SQ;
        #pragma unroll
        for (int p = 0; p < 32; ++p) {
            int i = tid + p * 256;
            int c = i >> 10, s = (i >> 9) & 1, r = (i >> 3) & 63, q = i & 7;
            const __nv_bfloat16* src = (s ? bl : bh) + (size_t)r * SQ + c * KC + q * 8;
            cp16(sb + 2 * (c * G4_BH + s * (64 * PITCH) + r * PITCH + q * 8), src);
        }
        CP_COMMIT();
    }

    // phase 1: row max.  lane-group of 8 per row; 4 passes over 128 rows.
    const int lrow = lane >> 3, lcol = lane & 7;
    float mrow[4];
    #pragma unroll
    for (int p = 0; p < 4; ++p) {
        const int row = p * 32 + wid * 4 + lrow;
        const float4* sp = (const float4*)(g_s + ((size_t)z * SQ + n0 + row) * SQ);
        float m = -1e30f;
        #pragma unroll
        for (int k = 0; k < 16; ++k) {
            float4 v = sp[lcol + k * 8];
            m = fmaxf(fmaxf(fmaxf(v.x, v.y), fmaxf(v.z, v.w)), m);
        }
        m = fmaxf(m, __shfl_xor_sync(0xffffffffu, m, 1));
        m = fmaxf(m, __shfl_xor_sync(0xffffffffu, m, 2));
        m = fmaxf(m, __shfl_xor_sync(0xffffffffu, m, 4));
        mrow[p] = m;
    }

    CP_WAIT(0);
    __syncthreads();

    float acc[2][4][4];
    #pragma unroll
    for (int f = 0; f < 2; f++)
        #pragma unroll
        for (int n = 0; n < 4; n++)
            #pragma unroll
            for (int j = 0; j < 4; j++) acc[f][n][j] = 0.f;
    float lsum[4] = {0.f, 0.f, 0.f, 0.f};

    const u32 a_off = (u32)(G4_BALL + (wm0 + (lane & 15)) * PITCH + ((lane < 16) ? 0 : 8));
    const u32 b_lane = (u32)((wn0 + (lane & 7) + ((lane >= 16) ? 8 : 0)) * PITCH
                             + ((lane & 8) ? 8 : 0));

    for (int c = 0; c < 8; ++c) {
        if (c) __syncthreads();
        // convert S[:, c*64 .. +64) -> p~ split bf16 into A smem
        #pragma unroll
        for (int p = 0; p < 4; ++p) {
            const int row = p * 32 + wid * 4 + lrow;
            const float4* sp = (const float4*)(g_s + ((size_t)z * SQ + n0 + row) * SQ + c * KC);
            float4 v0 = sp[lcol * 2], v1 = sp[lcol * 2 + 1];
            float e0 = __expf(v0.x - mrow[p]), e1 = __expf(v0.y - mrow[p]);
            float e2 = __expf(v0.z - mrow[p]), e3 = __expf(v0.w - mrow[p]);
            float e4 = __expf(v1.x - mrow[p]), e5 = __expf(v1.y - mrow[p]);
            float e6 = __expf(v1.z - mrow[p]), e7 = __expf(v1.w - mrow[p]);
            lsum[p] += ((e0 + e1) + (e2 + e3)) + ((e4 + e5) + (e6 + e7));
            u32 hp[4], lp[4];
            split2(e0, e1, hp[0], lp[0]);
            split2(e2, e3, hp[1], lp[1]);
            split2(e4, e5, hp[2], lp[2]);
            split2(e6, e7, hp[3], lp[3]);
            const u32 wbase = (u32)((G4_BALL + row * PITCH + lcol * 8) >> 1);
            #pragma unroll
            for (int j = 0; j < 4; ++j) {
                smw[wbase + j] = hp[j];
                smw[wbase + (G4_AH >> 1) + j] = lp[j];
            }
        }
        __syncthreads();

        const u32 bc = (u32)(c * G4_BH);
        #pragma unroll
        for (int t = 0; t < KC / 16; ++t) {
            u32 af[2][2][4];
            #pragma unroll
            for (int s = 0; s < 2; ++s)
                #pragma unroll
                for (int f = 0; f < 2; ++f)
                    ldm4(af[s][f], sb + 2 * (s * G4_AH + a_off + f * (16 * PITCH) + t * 16));
            u32 bf_[2][2][4];
            #pragma unroll
            for (int s = 0; s < 2; ++s)
                #pragma unroll
                for (int p = 0; p < 2; ++p)
                    ldm4(bf_[s][p], sb + 2 * (bc + s * (64 * PITCH) + b_lane + p * (16 * PITCH) + t * 16));
            #pragma unroll
            for (int f = 0; f < 2; ++f)
                #pragma unroll
                for (int n = 0; n < 4; ++n) {
                    const int p = n >> 1, hh = (n & 1) * 2;
                    mma16816(acc[f][n], af[0][f], bf_[0][p][hh], bf_[0][p][hh + 1]);
                }
            #pragma unroll
            for (int f = 0; f < 2; ++f)
                #pragma unroll
                for (int n = 0; n < 4; ++n) {
                    const int p = n >> 1, hh = (n & 1) * 2;
                    mma16816(acc[f][n], af[0][f], bf_[1][p][hh], bf_[1][p][hh + 1]);
                }
            #pragma unroll
            for (int f = 0; f < 2; ++f)
                #pragma unroll
                for (int n = 0; n < 4; ++n) {
                    const int p = n >> 1, hh = (n & 1) * 2;
                    mma16816(acc[f][n], af[1][f], bf_[0][p][hh], bf_[0][p][hh + 1]);
                }
        }
    }

    // finalize row sums -> 1/l
    #pragma unroll
    for (int p = 0; p < 4; ++p) {
        float s = lsum[p];
        s += __shfl_xor_sync(0xffffffffu, s, 1);
        s += __shfl_xor_sync(0xffffffffu, s, 2);
        s += __shfl_xor_sync(0xffffffffu, s, 4);
        if (lcol == 0) sm_linv[p * 32 + wid * 4 + lrow] = 1.0f / s;
    }
    __syncthreads();

    // epilogue: scale by 1/l, write out[b][n0+row][h*64 + col]
    const int g = lane >> 2, cc = lane & 3;
    #pragma unroll
    for (int f = 0; f < 2; ++f)
        #pragma unroll
        for (int n = 0; n < 4; ++n) {
            const int r0 = wm0 + f * 16 + g;
            const int r1 = r0 + 8;
            const int col = wn0 + n * 8 + cc * 2;
            const float* c4 = acc[f][n];
            const float li0 = sm_linv[r0], li1 = sm_linv[r1];
            *(float2*)(out + ((size_t)b * SQ + n0 + r0) * D_ + h * E_ + col)
                = make_float2(c4[0] * li0, c4[1] * li0);
            *(float2*)(out + ((size_t)b * SQ + n0 + r1) * D_ + h * E_ + col)
                = make_float2(c4[2] * li1, c4[3] * li1);
        }
}

// ---------------------------------------------------------------------------
// Prep kernels: fp32 -> (hi, lo) bf16 splits (+ transposes)
// ---------------------------------------------------------------------------
__global__ __launch_bounds__(256) void k_split_x(const float* __restrict__ x) {
    size_t i = ((size_t)blockIdx.x * 256 + threadIdx.x) * 4;
    if (i < (size_t)M1 * D_) {
        float4 v = *(const float4*)(x + i);
        float vv[4] = { v.x, v.y, v.z, v.w };
        __nv_bfloat16 hi[4], lo[4];
        #pragma unroll
        for (int j = 0; j < 4; ++j) {
            hi[j] = __float2bfloat16(vv[j]);
            lo[j] = __float2bfloat16(vv[j] - __bfloat162float(hi[j]));
        }
        *(uint2*)(g_x_hi + i) = *(uint2*)hi;
        *(uint2*)(g_x_lo + i) = *(uint2*)lo;
    }
}

// transpose Q[h][d][e] -> qt[h][e][d] and split.  grid(24,24,12), block(32,8)
__global__ __launch_bounds__(256) void k_split_qt(const float* __restrict__ Q) {
    __shared__ float t[32][33];
    const int h = blockIdx.z;
    const int d0 = blockIdx.y * 32, e0 = blockIdx.x * 32;
    const int x = threadIdx.x, y = threadIdx.y;
    const float* src = Q + (size_t)h * D_ * D_;
    #pragma unroll
    for (int i = 0; i < 32; i += 8)
        t[y + i][x] = src[(size_t)(d0 + y + i) * D_ + e0 + x];
    __syncthreads();
    __nv_bfloat16* oh = g_qt_hi + (size_t)h * D_ * D_;
    __nv_bfloat16* ol = g_qt_lo + (size_t)h * D_ * D_;
    #pragma unroll
    for (int i = 0; i < 32; i += 8) {
        float v = t[x][y + i];
        __nv_bfloat16 hh = __float2bfloat16(v);
        oh[(size_t)(e0 + y + i) * D_ + d0 + x] = hh;
        ol[(size_t)(e0 + y + i) * D_ + d0 + x] = __float2bfloat16(v - __bfloat162float(hh));
    }
}

// transpose V[h][d][e64] -> vt[h][e][d] and split.  grid(2,24,12), block(32,8)
__global__ __launch_bounds__(256) void k_split_vt(const float* __restrict__ V) {
    __shared__ float t[32][33];
    const int h = blockIdx.z;
    const int d0 = blockIdx.y * 32, e0 = blockIdx.x * 32;
    const int x = threadIdx.x, y = threadIdx.y;
    const float* src = V + (size_t)h * D_ * E_;
    #pragma unroll
    for (int i = 0; i < 32; i += 8)
        t[y + i][x] = src[(size_t)(d0 + y + i) * E_ + e0 + x];
    __syncthreads();
    __nv_bfloat16* oh = g_vt_hi + (size_t)h * E_ * D_;
    __nv_bfloat16* ol = g_vt_lo + (size_t)h * E_ * D_;
    #pragma unroll
    for (int i = 0; i < 32; i += 8) {
        float v = t[x][y + i];
        __nv_bfloat16 hh = __float2bfloat16(v);
        oh[(size_t)(e0 + y + i) * D_ + d0 + x] = hh;
        ol[(size_t)(e0 + y + i) * D_ + d0 + x] = __float2bfloat16(v - __bfloat162float(hh));
    }
}

// ---------------------------------------------------------------------------
extern "C" void kernel_launch(void* const* d_in, const int* in_sizes, int n_in,
                              void* d_out, int out_size) {
    (void)in_sizes; (void)n_in; (void)out_size;
    const float* x = (const float*)d_in[0];   // [32,512,768]
    const float* Q = (const float*)d_in[1];   // [12,768,768]
    const float* V = (const float*)d_in[2];   // [12,768,64]
    float* out = (float*)d_out;               // [32,512,768]

    cudaFuncSetAttribute(k_mma_g1,  cudaFuncAttributeMaxDynamicSharedMemorySize, SMEM_MMA);
    cudaFuncSetAttribute(k_mma_g2,  cudaFuncAttributeMaxDynamicSharedMemorySize, SMEM_MMA);
    cudaFuncSetAttribute(k_mma_g3,  cudaFuncAttributeMaxDynamicSharedMemorySize, SMEM_G3);
    cudaFuncSetAttribute(k_g4_fused, cudaFuncAttributeMaxDynamicSharedMemorySize, SMEM_G4);

    k_split_x <<<(int)(((size_t)M1 * D_ / 4 + 255) / 256), 256>>>(x);
    k_split_qt<<<dim3(24, 24, 12), dim3(32, 8)>>>(Q);
    k_split_vt<<<dim3(2, 24, 12),  dim3(32, 8)>>>(V);
    k_mma_g1  <<<dim3(6, 128, 12), GTHREADS, SMEM_MMA>>>();
    k_mma_g3  <<<dim3(4, 384), 256, SMEM_G3>>>();
    k_mma_g2  <<<dim3(4, 4, 384), GTHREADS, SMEM_MMA>>>();
    k_g4_fused<<<dim3(4, 384), 256, SMEM_G4>>>(out);
}

// round 17
// speedup vs baseline: 1.0214x; 1.0214x over previous
#include <cuda_runtime.h>
#include <cuda_bf16.h>

// Problem constants
#define B_  32
#define SQ  512
#define D_  768
#define H_  12
#define E_  64
#define M1  (B_*SQ)   // 16384

typedef unsigned long long u64;
typedef unsigned int u32;

// ---------------------------------------------------------------------------
// Scratch (device globals per harness rules — no allocations allowed)
// ---------------------------------------------------------------------------
__device__ __nv_bfloat16 g_x_hi [(size_t)M1 * D_];          // 25 MB
__device__ __nv_bfloat16 g_x_lo [(size_t)M1 * D_];          // 25 MB
__device__ __nv_bfloat16 g_qt_hi[(size_t)H_ * D_ * D_];     // 14 MB  (Q^T: [h][e][d])
__device__ __nv_bfloat16 g_qt_lo[(size_t)H_ * D_ * D_];     // 14 MB
__device__ __nv_bfloat16 g_vt_hi[(size_t)H_ * E_ * D_];     // 1.2 MB (V^T: [h][e][d])
__device__ __nv_bfloat16 g_vt_lo[(size_t)H_ * E_ * D_];
__device__ __nv_bfloat16 g_q_hi [(size_t)H_ * M1 * D_];     // 302 MB (q split, K-major for G2)
__device__ __nv_bfloat16 g_q_lo [(size_t)H_ * M1 * D_];     // 302 MB
__device__ float g_s [(size_t)B_ * H_ * SQ * SQ];           // 402 MB
__device__ __nv_bfloat16 g_xvt_hi[(size_t)B_ * H_ * E_ * SQ]; // 25 MB (xv^T: [z][e][m])
__device__ __nv_bfloat16 g_xvt_lo[(size_t)B_ * H_ * E_ * SQ];

// ---------------------------------------------------------------------------
// Portable (compute_103 baseline) tensor-core + async-copy helpers
// ---------------------------------------------------------------------------
__device__ __forceinline__ u32 smem_u32(const void* p) {
    u32 a;
    asm("{ .reg .u64 t; cvta.to.shared.u64 t, %1; cvt.u32.u64 %0, t; }" : "=r"(a) : "l"(p));
    return a;
}
__device__ __forceinline__ void cp16(u32 dst, const void* src) {
    asm volatile("cp.async.cg.shared.global [%0], [%1], 16;" :: "r"(dst), "l"(src) : "memory");
}
#define CP_COMMIT() asm volatile("cp.async.commit_group;" ::: "memory")
#define CP_WAIT(n)  asm volatile("cp.async.wait_group %0;" :: "n"(n) : "memory")

__device__ __forceinline__ void ldm4(u32* r, u32 addr) {
    asm volatile("ldmatrix.sync.aligned.m8n8.x4.shared.b16 {%0,%1,%2,%3}, [%4];"
        : "=r"(r[0]), "=r"(r[1]), "=r"(r[2]), "=r"(r[3]) : "r"(addr));
}
__device__ __forceinline__ void mma16816(float* c, const u32* a, u32 b0, u32 b1) {
    asm volatile(
        "mma.sync.aligned.m16n8k16.row.col.f32.bf16.bf16.f32 "
        "{%0,%1,%2,%3}, {%4,%5,%6,%7}, {%8,%9}, {%0,%1,%2,%3};"
        : "+f"(c[0]), "+f"(c[1]), "+f"(c[2]), "+f"(c[3])
        : "r"(a[0]), "r"(a[1]), "r"(a[2]), "r"(a[3]), "r"(b0), "r"(b1));
}
__device__ __forceinline__ void split2(float f0, float f1, u32& hp, u32& lp) {
    __nv_bfloat16 h0 = __float2bfloat16(f0);
    __nv_bfloat16 h1 = __float2bfloat16(f1);
    __nv_bfloat16 l0 = __float2bfloat16(f0 - __bfloat162float(h0));
    __nv_bfloat16 l1 = __float2bfloat16(f1 - __bfloat162float(h1));
    hp = (u32)__bfloat16_as_ushort(h0) | ((u32)__bfloat16_as_ushort(h1) << 16);
    lp = (u32)__bfloat16_as_ushort(l0) | ((u32)__bfloat16_as_ushort(l1) << 16);
}

// ---------------------------------------------------------------------------
// Persistent mma.sync GEMM: per tile C[128,128] = A[128,768] * B[128,768]^T
// (split-bf16, 3 products). 512 threads = 16 warps (4m x 4n), warp tile 32x32.
// 3-stage cp.async ring runs over a FLAT (tile, chunk) stream so the pipeline
// never drains at tile boundaries; epilogue (regs only) overlaps prefetch.
// Tile mapping supplied via functor structs (no --extended-lambda available).
// ---------------------------------------------------------------------------
#define KC     64
#define NCH    (D_/KC)               // 12 chunks per tile
#define PITCH  72                    // halves per smem row (64 + 8 pad)
#define ARR    (128*PITCH)
#define BUFH   (4*ARR)               // halves per stage (Ahi,Alo,Bhi,Blo)
#define NSTG   3
#define SMEM_MMA (NSTG*BUFH*2)       // 221184 bytes
#define GTHREADS 512

struct TP {
    const __nv_bfloat16 *Ahi, *Alo, *Bhi, *Blo;
    __nv_bfloat16 *ohi, *olo;
    float *of;
};

// G1 tile mapping: t -> (nx in 0..5, my in 0..127, h in 0..11)
struct TileG1 {
    static __device__ __forceinline__ TP get(int t) {
        TP tp;
        const int nx = t % 6;
        const int r  = t / 6;
        const int my = r & 127;
        const int h  = r >> 7;
        const size_t m0 = (size_t)my * 128, n0 = (size_t)nx * 128;
        tp.Ahi = g_x_hi + m0 * D_;
        tp.Alo = g_x_lo + m0 * D_;
        tp.Bhi = g_qt_hi + ((size_t)h * D_ + n0) * D_;
        tp.Blo = g_qt_lo + ((size_t)h * D_ + n0) * D_;
        tp.ohi = g_q_hi + (size_t)h * M1 * D_ + m0 * D_ + n0;
        tp.olo = g_q_lo + (size_t)h * M1 * D_ + m0 * D_ + n0;
        tp.of  = nullptr;
        return tp;
    }
};

// G2 tile mapping: t -> (mx, my in 0..3, z in 0..383)
struct TileG2 {
    static __device__ __forceinline__ TP get(int t) {
        TP tp;
        const int mx = t & 3;
        const int my = (t >> 2) & 3;
        const int z  = t >> 4;
        const int b = z / H_, h = z % H_;
        const size_t m0 = (size_t)my * 128;
        const size_t n0 = (size_t)mx * 128;
        const size_t arow = (size_t)h * M1 * D_ + ((size_t)b * SQ + m0) * D_;
        const size_t brow = ((size_t)b * SQ + n0) * D_;
        tp.Ahi = g_q_hi + arow;
        tp.Alo = g_q_lo + arow;
        tp.Bhi = g_x_hi + brow;
        tp.Blo = g_x_lo + brow;
        tp.ohi = nullptr; tp.olo = nullptr;
        tp.of  = g_s + (size_t)z * SQ * SQ + m0 * SQ + n0;
        return tp;
    }
};

template<int MODE, class TF>   // MODE 0: split-bf16 output (G1); 1: fp32 (G2)
__device__ __forceinline__ void mma_persist(int ntiles)
{
    extern __shared__ __align__(16) char smem[];
    const u32 sb = smem_u32(smem);
    const int tid = threadIdx.x, lane = tid & 31, wid = tid >> 5;
    const int wm0 = (wid >> 2) * 32;
    const int wn0 = (wid & 3) * 32;
    const int ldo = (MODE == 0) ? D_ : SQ;

    const int nmine = (ntiles - (int)blockIdx.x + (int)gridDim.x - 1) / (int)gridDim.x;
    if (nmine <= 0) return;
    const int total = nmine * NCH;       // flat chunk stream length

    float acc[2][4][4];
    #pragma unroll
    for (int f = 0; f < 2; f++)
        #pragma unroll
        for (int n = 0; n < 4; n++)
            #pragma unroll
            for (int j = 0; j < 4; j++) acc[f][n][j] = 0.f;

    const u32 a_off = (u32)((wm0 + (lane & 15)) * PITCH + ((lane < 16) ? 0 : 8));
    const u32 b_off = (u32)(2 * ARR + (wn0 + (lane & 7) + ((lane >= 16) ? 8 : 0)) * PITCH
                            + ((lane & 8) ? 8 : 0));

    // chunk loader over the flat stream
    auto load_chunk = [&](int s) {
        const int t = (int)blockIdx.x + (s / NCH) * (int)gridDim.x;
        const int c = s % NCH;
        TP tp = TF::get(t);
        const __nv_bfloat16* srcs[4] = { tp.Ahi, tp.Alo, tp.Bhi, tp.Blo };
        const int buf = s % NSTG;
        #pragma unroll
        for (int a4 = 0; a4 < 4; ++a4) {
            u32 dbase = sb + buf * (BUFH * 2) + a4 * (ARR * 2);
            const __nv_bfloat16* sp = srcs[a4] + (size_t)c * KC;
            #pragma unroll
            for (int p = 0; p < 2; ++p) {
                int i = tid + p * GTHREADS;
                int r = i >> 3, q = i & 7;
                cp16(dbase + r * (PITCH * 2) + q * 16, sp + (size_t)r * D_ + q * 8);
            }
        }
    };

    load_chunk(0); CP_COMMIT();
    if (total > 1) { load_chunk(1); CP_COMMIT(); }

    for (int s = 0; s < total; ++s) {
        if (s + 1 < total) { CP_WAIT(1); } else { CP_WAIT(0); }
        __syncthreads();
        if (s + 2 < total) { load_chunk(s + 2); CP_COMMIT(); }

        const u32 base = sb + (s % NSTG) * (BUFH * 2);
        #pragma unroll
        for (int t = 0; t < KC / 16; ++t) {
            u32 af[2][2][4];
            #pragma unroll
            for (int ss = 0; ss < 2; ++ss)
                #pragma unroll
                for (int f = 0; f < 2; ++f)
                    ldm4(af[ss][f], base + 2 * (ss * ARR + a_off + f * (16 * PITCH) + t * 16));
            u32 bf_[2][2][4];
            #pragma unroll
            for (int ss = 0; ss < 2; ++ss)
                #pragma unroll
                for (int p = 0; p < 2; ++p)
                    ldm4(bf_[ss][p], base + 2 * (ss * ARR + b_off + p * (16 * PITCH) + t * 16));

            // product-major ordering (keeps 8-way acc ILP)
            #pragma unroll
            for (int f = 0; f < 2; ++f)
                #pragma unroll
                for (int n = 0; n < 4; ++n) {
                    const int p = n >> 1, hh = (n & 1) * 2;
                    mma16816(acc[f][n], af[0][f], bf_[0][p][hh], bf_[0][p][hh + 1]); // hi*hi
                }
            #pragma unroll
            for (int f = 0; f < 2; ++f)
                #pragma unroll
                for (int n = 0; n < 4; ++n) {
                    const int p = n >> 1, hh = (n & 1) * 2;
                    mma16816(acc[f][n], af[0][f], bf_[1][p][hh], bf_[1][p][hh + 1]); // hi*lo
                }
            #pragma unroll
            for (int f = 0; f < 2; ++f)
                #pragma unroll
                for (int n = 0; n < 4; ++n) {
                    const int p = n >> 1, hh = (n & 1) * 2;
                    mma16816(acc[f][n], af[1][f], bf_[0][p][hh], bf_[0][p][hh + 1]); // lo*hi
                }
        }

        if (s % NCH == NCH - 1) {
            // tile finished: epilogue from regs (no smem, no extra sync);
            // overlaps with in-flight cp.async for the next tile's chunks.
            TP tp = TF::get((int)blockIdx.x + (s / NCH) * (int)gridDim.x);
            const int g = lane >> 2, cc = lane & 3;
            #pragma unroll
            for (int f = 0; f < 2; ++f)
                #pragma unroll
                for (int n = 0; n < 4; ++n) {
                    const int r0 = wm0 + f * 16 + g;
                    const int r1 = r0 + 8;
                    const int col = wn0 + n * 8 + cc * 2;
                    float* c4 = acc[f][n];
                    if (MODE == 0) {
                        u32 hp, lp;
                        split2(c4[0], c4[1], hp, lp);
                        *(u32*)(tp.ohi + (size_t)r0 * ldo + col) = hp;
                        *(u32*)(tp.olo + (size_t)r0 * ldo + col) = lp;
                        split2(c4[2], c4[3], hp, lp);
                        *(u32*)(tp.ohi + (size_t)r1 * ldo + col) = hp;
                        *(u32*)(tp.olo + (size_t)r1 * ldo + col) = lp;
                    } else {
                        *(float2*)(tp.of + (size_t)r0 * ldo + col) = make_float2(c4[0], c4[1]);
                        *(float2*)(tp.of + (size_t)r1 * ldo + col) = make_float2(c4[2], c4[3]);
                    }
                    c4[0] = 0.f; c4[1] = 0.f; c4[2] = 0.f; c4[3] = 0.f;
                }
        }
    }
}

// G1: q[h][m][n] = x[m][:] . qt[h][n][:]   (9216 tiles, persistent grid)
__global__ __launch_bounds__(GTHREADS, 1) void k_mma_g1() {
    mma_persist<0, TileG1>(9216);
}

// G2: S[b,h][n][m] = q[h][b*512+n][:] . x[b*512+m][:]   (6144 tiles)
__global__ __launch_bounds__(GTHREADS, 1) void k_mma_g2() {
    mma_persist<1, TileG2>(6144);
}

// ---------------------------------------------------------------------------
// G3 (mma): xv^T[z][e][m] = (x_b[m][:] . vt[h][e][:])^T   tile 128m x 64e
// 8 warps (4m x 2n), warp tile 32x32, 2-stage cp.async. grid(4, 384)
// ---------------------------------------------------------------------------
#define S3AH (128*PITCH)             // halves per A split array
#define S3BH (64*PITCH)              // halves per B split array
#define S3H  (2*S3AH + 2*S3BH)       // stage halves = 27648
#define SMEM_G3 (2*S3H*2)            // 110592 bytes

__global__ __launch_bounds__(256, 1) void k_mma_g3() {
    extern __shared__ __align__(16) char smem[];
    const u32 sb = smem_u32(smem);
    const int z = blockIdx.y, b = z / H_, h = z % H_;
    const size_t m0 = (size_t)blockIdx.x * 128;
    const int tid = threadIdx.x, lane = tid & 31, wid = tid >> 5;
    const int wm0 = (wid >> 1) * 32;
    const int wn0 = (wid & 1) * 32;

    const __nv_bfloat16* Ahi = g_x_hi + ((size_t)b * SQ + m0) * D_;
    const __nv_bfloat16* Alo = g_x_lo + ((size_t)b * SQ + m0) * D_;
    const __nv_bfloat16* Bhi = g_vt_hi + (size_t)h * E_ * D_;
    const __nv_bfloat16* Blo = g_vt_lo + (size_t)h * E_ * D_;

    float acc[2][4][4];
    #pragma unroll
    for (int f = 0; f < 2; f++)
        #pragma unroll
        for (int n = 0; n < 4; n++)
            #pragma unroll
            for (int j = 0; j < 4; j++) acc[f][n][j] = 0.f;

    auto load_stage = [&](int buf, int c) {
        const u32 db = sb + buf * (S3H * 2);
        #pragma unroll
        for (int p = 0; p < 8; ++p) {        // A: 2 splits x 128 rows x 8 quads
            int i = tid + p * 256;
            int s = i >> 10, r = (i >> 3) & 127, q = i & 7;
            const __nv_bfloat16* src = (s ? Alo : Ahi) + (size_t)r * D_ + c * KC + q * 8;
            cp16(db + 2 * (s * S3AH + r * PITCH + q * 8), src);
        }
        #pragma unroll
        for (int p = 0; p < 4; ++p) {        // B: 2 splits x 64 rows x 8 quads
            int i = tid + p * 256;
            int s = i >> 9, r = (i >> 3) & 63, q = i & 7;
            const __nv_bfloat16* src = (s ? Blo : Bhi) + (size_t)r * D_ + c * KC + q * 8;
            cp16(db + 2 * (2 * S3AH + s * S3BH + r * PITCH + q * 8), src);
        }
    };

    const u32 a_off = (u32)((wm0 + (lane & 15)) * PITCH + ((lane < 16) ? 0 : 8));
    const u32 b_off = (u32)(2 * S3AH + (wn0 + (lane & 7) + ((lane >= 16) ? 8 : 0)) * PITCH
                            + ((lane & 8) ? 8 : 0));

    load_stage(0, 0); CP_COMMIT();
    for (int c = 0; c < NCH; ++c) {
        const int buf = c & 1;
        if (c + 1 < NCH) { load_stage(buf ^ 1, c + 1); CP_COMMIT(); CP_WAIT(1); }
        else             { CP_WAIT(0); }
        __syncthreads();
        const u32 base = sb + buf * (S3H * 2);
        #pragma unroll
        for (int t = 0; t < KC / 16; ++t) {
            u32 af[2][2][4];
            #pragma unroll
            for (int s = 0; s < 2; ++s)
                #pragma unroll
                for (int f = 0; f < 2; ++f)
                    ldm4(af[s][f], base + 2 * (s * S3AH + a_off + f * (16 * PITCH) + t * 16));
            u32 bf_[2][2][4];
            #pragma unroll
            for (int s = 0; s < 2; ++s)
                #pragma unroll
                for (int p = 0; p < 2; ++p)
                    ldm4(bf_[s][p], base + 2 * (s * S3BH + b_off + p * (16 * PITCH) + t * 16));
            #pragma unroll
            for (int f = 0; f < 2; ++f)
                #pragma unroll
                for (int n = 0; n < 4; ++n) {
                    const int p = n >> 1, hh = (n & 1) * 2;
                    mma16816(acc[f][n], af[0][f], bf_[0][p][hh], bf_[0][p][hh + 1]);
                }
            #pragma unroll
            for (int f = 0; f < 2; ++f)
                #pragma unroll
                for (int n = 0; n < 4; ++n) {
                    const int p = n >> 1, hh = (n & 1) * 2;
                    mma16816(acc[f][n], af[0][f], bf_[1][p][hh], bf_[1][p][hh + 1]);
                }
            #pragma unroll
            for (int f = 0; f < 2; ++f)
                #pragma unroll
                for (int n = 0; n < 4; ++n) {
                    const int p = n >> 1, hh = (n & 1) * 2;
                    mma16816(acc[f][n], af[1][f], bf_[0][p][hh], bf_[0][p][hh + 1]);
                }
        }
        __syncthreads();
    }

    // transposed split epilogue -> xvt[z][e][m]
    const int g = lane >> 2, cc = lane & 3;
    __nv_bfloat16* oh = g_xvt_hi + (size_t)z * E_ * SQ;
    __nv_bfloat16* ol = g_xvt_lo + (size_t)z * E_ * SQ;
    #pragma unroll
    for (int f = 0; f < 2; ++f)
        #pragma unroll
        for (int n = 0; n < 4; ++n) {
            const int r0 = wm0 + f * 16 + g;
            const int r1 = r0 + 8;
            const int col = wn0 + n * 8 + cc * 2;
            const float* c4 = acc[f][n];
            #pragma unroll
            for (int j = 0; j < 4; ++j) {
                const int r = (j < 2) ? r0 : r1;
                const int cl = col + (j & 1);
                float v = c4[j];
                __nv_bfloat16 hi = __float2bfloat16(v);
                oh[(size_t)cl * SQ + m0 + r] = hi;
                ol[(size_t)cl * SQ + m0 + r] = __float2bfloat16(v - __bfloat162float(hi));
            }
        }
}

// ---------------------------------------------------------------------------
// G4 fused: out_tile = softmax(S_tile_rows) @ xv   per (z, 128-query-block)
// 8 warps (4m x 2n), warp tile 32x32. B (xv^T) fully preloaded; A (p-tilde)
// converted chunk-by-chunk from S with deferred 1/l normalization. grid(4, 384)
// ---------------------------------------------------------------------------
#define G4_BH   (2*64*PITCH)                 // halves per B chunk (2 splits)
#define G4_BALL (8*G4_BH)                    // 73728 halves
#define G4_AH   (128*PITCH)                  // halves per A split
#define G4_LOFF ((G4_BALL + 2*G4_AH)*2)      // byte offset of linv[128]
#define SMEM_G4 (G4_LOFF + 128*4)            // 184832 bytes

__global__ __launch_bounds__(256, 1) void k_g4_fused(float* __restrict__ out) {
    extern __shared__ __align__(16) char smem[];
    const u32 sb = smem_u32(smem);
    u32* smw = (u32*)smem;
    float* sm_linv = (float*)(smem + G4_LOFF);

    const int z = blockIdx.y, b = z / H_, h = z % H_;
    const int n0 = blockIdx.x * 128;
    const int tid = threadIdx.x, lane = tid & 31, wid = tid >> 5;
    const int wm0 = (wid >> 1) * 32;
    const int wn0 = (wid & 1) * 32;

    // preload all of B = xvt[z] (64 x 512, 2 splits) via cp.async
    {
        const __nv_bfloat16* bh = g_xvt_hi + (size_t)z * E_ * SQ;
        const __nv_bfloat16* bl = g_xvt_lo + (size_t)z * E_ * SQ;
        #pragma unroll
        for (int p = 0; p < 32; ++p) {
            int i = tid + p * 256;
            int c = i >> 10, s = (i >> 9) & 1, r = (i >> 3) & 63, q = i & 7;
            const __nv_bfloat16* src = (s ? bl : bh) + (size_t)r * SQ + c * KC + q * 8;
            cp16(sb + 2 * (c * G4_BH + s * (64 * PITCH) + r * PITCH + q * 8), src);
        }
        CP_COMMIT();
    }

    // phase 1: row max.  lane-group of 8 per row; 4 passes over 128 rows.
    const int lrow = lane >> 3, lcol = lane & 7;
    float mrow[4];
    #pragma unroll
    for (int p = 0; p < 4; ++p) {
        const int row = p * 32 + wid * 4 + lrow;
        const float4* sp = (const float4*)(g_s + ((size_t)z * SQ + n0 + row) * SQ);
        float m = -1e30f;
        #pragma unroll
        for (int k = 0; k < 16; ++k) {
            float4 v = sp[lcol + k * 8];
            m = fmaxf(fmaxf(fmaxf(v.x, v.y), fmaxf(v.z, v.w)), m);
        }
        m = fmaxf(m, __shfl_xor_sync(0xffffffffu, m, 1));
        m = fmaxf(m, __shfl_xor_sync(0xffffffffu, m, 2));
        m = fmaxf(m, __shfl_xor_sync(0xffffffffu, m, 4));
        mrow[p] = m;
    }

    CP_WAIT(0);
    __syncthreads();

    float acc[2][4][4];
    #pragma unroll
    for (int f = 0; f < 2; f++)
        #pragma unroll
        for (int n = 0; n < 4; n++)
            #pragma unroll
            for (int j = 0; j < 4; j++) acc[f][n][j] = 0.f;
    float lsum[4] = {0.f, 0.f, 0.f, 0.f};

    const u32 a_off = (u32)(G4_BALL + (wm0 + (lane & 15)) * PITCH + ((lane < 16) ? 0 : 8));
    const u32 b_lane = (u32)((wn0 + (lane & 7) + ((lane >= 16) ? 8 : 0)) * PITCH
                             + ((lane & 8) ? 8 : 0));

    for (int c = 0; c < 8; ++c) {
        if (c) __syncthreads();
        // convert S[:, c*64 .. +64) -> p~ split bf16 into A smem
        #pragma unroll
        for (int p = 0; p < 4; ++p) {
            const int row = p * 32 + wid * 4 + lrow;
            const float4* sp = (const float4*)(g_s + ((size_t)z * SQ + n0 + row) * SQ + c * KC);
            float4 v0 = sp[lcol * 2], v1 = sp[lcol * 2 + 1];
            float e0 = __expf(v0.x - mrow[p]), e1 = __expf(v0.y - mrow[p]);
            float e2 = __expf(v0.z - mrow[p]), e3 = __expf(v0.w - mrow[p]);
            float e4 = __expf(v1.x - mrow[p]), e5 = __expf(v1.y - mrow[p]);
            float e6 = __expf(v1.z - mrow[p]), e7 = __expf(v1.w - mrow[p]);
            lsum[p] += ((e0 + e1) + (e2 + e3)) + ((e4 + e5) + (e6 + e7));
            u32 hp[4], lp[4];
            split2(e0, e1, hp[0], lp[0]);
            split2(e2, e3, hp[1], lp[1]);
            split2(e4, e5, hp[2], lp[2]);
            split2(e6, e7, hp[3], lp[3]);
            const u32 wbase = (u32)((G4_BALL + row * PITCH + lcol * 8) >> 1);
            #pragma unroll
            for (int j = 0; j < 4; ++j) {
                smw[wbase + j] = hp[j];
                smw[wbase + (G4_AH >> 1) + j] = lp[j];
            }
        }
        __syncthreads();

        const u32 bc = (u32)(c * G4_BH);
        #pragma unroll
        for (int t = 0; t < KC / 16; ++t) {
            u32 af[2][2][4];
            #pragma unroll
            for (int s = 0; s < 2; ++s)
                #pragma unroll
                for (int f = 0; f < 2; ++f)
                    ldm4(af[s][f], sb + 2 * (s * G4_AH + a_off + f * (16 * PITCH) + t * 16));
            u32 bf_[2][2][4];
            #pragma unroll
            for (int s = 0; s < 2; ++s)
                #pragma unroll
                for (int p = 0; p < 2; ++p)
                    ldm4(bf_[s][p], sb + 2 * (bc + s * (64 * PITCH) + b_lane + p * (16 * PITCH) + t * 16));
            #pragma unroll
            for (int f = 0; f < 2; ++f)
                #pragma unroll
                for (int n = 0; n < 4; ++n) {
                    const int p = n >> 1, hh = (n & 1) * 2;
                    mma16816(acc[f][n], af[0][f], bf_[0][p][hh], bf_[0][p][hh + 1]);
                }
            #pragma unroll
            for (int f = 0; f < 2; ++f)
                #pragma unroll
                for (int n = 0; n < 4; ++n) {
                    const int p = n >> 1, hh = (n & 1) * 2;
                    mma16816(acc[f][n], af[0][f], bf_[1][p][hh], bf_[1][p][hh + 1]);
                }
            #pragma unroll
            for (int f = 0; f < 2; ++f)
                #pragma unroll
                for (int n = 0; n < 4; ++n) {
                    const int p = n >> 1, hh = (n & 1) * 2;
                    mma16816(acc[f][n], af[1][f], bf_[0][p][hh], bf_[0][p][hh + 1]);
                }
        }
    }

    // finalize row sums -> 1/l
    #pragma unroll
    for (int p = 0; p < 4; ++p) {
        float s = lsum[p];
        s += __shfl_xor_sync(0xffffffffu, s, 1);
        s += __shfl_xor_sync(0xffffffffu, s, 2);
        s += __shfl_xor_sync(0xffffffffu, s, 4);
        if (lcol == 0) sm_linv[p * 32 + wid * 4 + lrow] = 1.0f / s;
    }
    __syncthreads();

    // epilogue: scale by 1/l, write out[b][n0+row][h*64 + col]
    const int g = lane >> 2, cc = lane & 3;
    #pragma unroll
    for (int f = 0; f < 2; ++f)
        #pragma unroll
        for (int n = 0; n < 4; ++n) {
            const int r0 = wm0 + f * 16 + g;
            const int r1 = r0 + 8;
            const int col = wn0 + n * 8 + cc * 2;
            const float* c4 = acc[f][n];
            const float li0 = sm_linv[r0], li1 = sm_linv[r1];
            *(float2*)(out + ((size_t)b * SQ + n0 + r0) * D_ + h * E_ + col)
                = make_float2(c4[0] * li0, c4[1] * li0);
            *(float2*)(out + ((size_t)b * SQ + n0 + r1) * D_ + h * E_ + col)
                = make_float2(c4[2] * li1, c4[3] * li1);
        }
}

// ---------------------------------------------------------------------------
// Prep kernels: fp32 -> (hi, lo) bf16 splits (+ transposes)
// ---------------------------------------------------------------------------
__global__ __launch_bounds__(256) void k_split_x(const float* __restrict__ x) {
    size_t i = ((size_t)blockIdx.x * 256 + threadIdx.x) * 4;
    if (i < (size_t)M1 * D_) {
        float4 v = *(const float4*)(x + i);
        float vv[4] = { v.x, v.y, v.z, v.w };
        __nv_bfloat16 hi[4], lo[4];
        #pragma unroll
        for (int j = 0; j < 4; ++j) {
            hi[j] = __float2bfloat16(vv[j]);
            lo[j] = __float2bfloat16(vv[j] - __bfloat162float(hi[j]));
        }
        *(uint2*)(g_x_hi + i) = *(uint2*)hi;
        *(uint2*)(g_x_lo + i) = *(uint2*)lo;
    }
}

// transpose Q[h][d][e] -> qt[h][e][d] and split.  grid(24,24,12), block(32,8)
__global__ __launch_bounds__(256) void k_split_qt(const float* __restrict__ Q) {
    __shared__ float t[32][33];
    const int h = blockIdx.z;
    const int d0 = blockIdx.y * 32, e0 = blockIdx.x * 32;
    const int x = threadIdx.x, y = threadIdx.y;
    const float* src = Q + (size_t)h * D_ * D_;
    #pragma unroll
    for (int i = 0; i < 32; i += 8)
        t[y + i][x] = src[(size_t)(d0 + y + i) * D_ + e0 + x];
    __syncthreads();
    __nv_bfloat16* oh = g_qt_hi + (size_t)h * D_ * D_;
    __nv_bfloat16* ol = g_qt_lo + (size_t)h * D_ * D_;
    #pragma unroll
    for (int i = 0; i < 32; i += 8) {
        float v = t[x][y + i];
        __nv_bfloat16 hh = __float2bfloat16(v);
        oh[(size_t)(e0 + y + i) * D_ + d0 + x] = hh;
        ol[(size_t)(e0 + y + i) * D_ + d0 + x] = __float2bfloat16(v - __bfloat162float(hh));
    }
}

// transpose V[h][d][e64] -> vt[h][e][d] and split.  grid(2,24,12), block(32,8)
__global__ __launch_bounds__(256) void k_split_vt(const float* __restrict__ V) {
    __shared__ float t[32][33];
    const int h = blockIdx.z;
    const int d0 = blockIdx.y * 32, e0 = blockIdx.x * 32;
    const int x = threadIdx.x, y = threadIdx.y;
    const float* src = V + (size_t)h * D_ * E_;
    #pragma unroll
    for (int i = 0; i < 32; i += 8)
        t[y + i][x] = src[(size_t)(d0 + y + i) * E_ + e0 + x];
    __syncthreads();
    __nv_bfloat16* oh = g_vt_hi + (size_t)h * E_ * D_;
    __nv_bfloat16* ol = g_vt_lo + (size_t)h * E_ * D_;
    #pragma unroll
    for (int i = 0; i < 32; i += 8) {
        float v = t[x][y + i];
        __nv_bfloat16 hh = __float2bfloat16(v);
        oh[(size_t)(e0 + y + i) * D_ + d0 + x] = hh;
        ol[(size_t)(e0 + y + i) * D_ + d0 + x] = __float2bfloat16(v - __bfloat162float(hh));
    }
}

// ---------------------------------------------------------------------------
extern "C" void kernel_launch(void* const* d_in, const int* in_sizes, int n_in,
                              void* d_out, int out_size) {
    (void)in_sizes; (void)n_in; (void)out_size;
    const float* x = (const float*)d_in[0];   // [32,512,768]
    const float* Q = (const float*)d_in[1];   // [12,768,768]
    const float* V = (const float*)d_in[2];   // [12,768,64]
    float* out = (float*)d_out;               // [32,512,768]

    int nsm = 148;
    cudaDeviceGetAttribute(&nsm, cudaDevAttrMultiProcessorCount, 0);

    cudaFuncSetAttribute(k_mma_g1,  cudaFuncAttributeMaxDynamicSharedMemorySize, SMEM_MMA);
    cudaFuncSetAttribute(k_mma_g2,  cudaFuncAttributeMaxDynamicSharedMemorySize, SMEM_MMA);
    cudaFuncSetAttribute(k_mma_g3,  cudaFuncAttributeMaxDynamicSharedMemorySize, SMEM_G3);
    cudaFuncSetAttribute(k_g4_fused, cudaFuncAttributeMaxDynamicSharedMemorySize, SMEM_G4);

    k_split_x <<<(int)(((size_t)M1 * D_ / 4 + 255) / 256), 256>>>(x);
    k_split_qt<<<dim3(24, 24, 12), dim3(32, 8)>>>(Q);
    k_split_vt<<<dim3(2, 24, 12),  dim3(32, 8)>>>(V);
    k_mma_g1  <<<nsm, GTHREADS, SMEM_MMA>>>();
    k_mma_g3  <<<dim3(4, 384), 256, SMEM_G3>>>();
    k_mma_g2  <<<nsm, GTHREADS, SMEM_MMA>>>();
    k_g4_fused<<<dim3(4, 384), 256, SMEM_G4>>>(out);
}